// round 8
// baseline (speedup 1.0000x reference)
#include <cuda_runtime.h>
#include <math.h>

#define T 4096
#define E 300
#define HID 512
#define G4 2048          // 4*HID
#define TAGS 12
#define NEGV -10000.0f
#define NB 32            // persistent blocks per direction in LSTM kernel

// ---------------- static device scratch (no allocations allowed) ----------------
__device__ float d_xg[2][T * G4];                  // 2 x 32 MB: precomputed input projections
__device__ unsigned long long d_Hx[2][T * HID];    // packed (tag<<32 | h_bits); tag = t+1
__device__ float d_feats[T * TAGS];
__device__ unsigned long long d_bp[T];             // packed backpointers: 12 nibbles per step

// fma.rn.f32x2: packed dual FP32 FMA (FFMA2). Cleared by R3/R4 control:
// identical numerics to scalar FFMA.
#define FMA2(d, a, b, c) \
    asm("fma.rn.f32x2 %0, %1, %2, %3;" : "=l"(d) : "l"(a), "l"(b), "l"(c))

// ---------------- zero d_Hx (graph replays must redo identical work) ----------------
__global__ void init_kernel() {
    unsigned int i = blockIdx.x * 1024 + threadIdx.x;    // 2M float4s = 32MB
    ((float4*)d_Hx)[i] = make_float4(0.f, 0.f, 0.f, 0.f);
}

// ---------------- xg = emb[sentence] @ Wih^T + (bih + bhh) ----------------
// grid (T/32, 2048/256), block 256. Each block: 32 timesteps x 256 rows.
__global__ void __launch_bounds__(256) xg_kernel(
    int dir,
    const int*   __restrict__ sent,
    const float* __restrict__ embt,
    const float* __restrict__ Wih,
    const float* __restrict__ bih,
    const float* __restrict__ bhh)
{
    __shared__ __align__(16) float es[E * 32];   // es[k*32 + t]
    int t0 = blockIdx.x * 32;
    for (int i = threadIdx.x; i < 32 * E; i += 256) {
        int tt = i / E, k = i - tt * E;
        es[k * 32 + tt] = embt[(long long)sent[t0 + tt] * E + k];
    }
    __syncthreads();

    int r = blockIdx.y * 256 + threadIdx.x;
    const float* w = Wih + (long long)r * E;
    float bias = bih[r] + bhh[r];
    float acc[32];
#pragma unroll
    for (int t = 0; t < 32; t++) acc[t] = bias;

    for (int k = 0; k < E; k++) {
        float wv = __ldg(w + k);
        const float4* e4 = (const float4*)(es + k * 32);
#pragma unroll
        for (int q = 0; q < 8; q++) {
            float4 e = e4[q];
            acc[4 * q + 0] += wv * e.x;
            acc[4 * q + 1] += wv * e.y;
            acc[4 * q + 2] += wv * e.z;
            acc[4 * q + 3] += wv * e.w;
        }
    }
    float* xg = d_xg[dir];
#pragma unroll
    for (int t = 0; t < 32; t++)
        xg[(long long)(t0 + t) * G4 + r] = acc[t];
}

// ---------------- persistent BiLSTM recurrence ----------------
// 64 blocks (32 fwd, 32 bwd), 256 threads; all co-resident.
// Block b owns 16 hidden units -> 64 Whh gate rows.
// Warp w: col chunk cc=w>>1 (128 cols), local gate row lr=(w&1)*32+l.
// Per step:
//   all warps: FFMA2 partial dots -> part[4][64] -> syncA
//   warp 0 lanes<16: reduce + activations; each lane does ONE
//       st.release.gpu.u64 of (t+1)<<32 | h_bits (16 lanes, 128B coalesced).
//       Strong pair ops are morally strong -> single-copy atomic BY SPEC:
//       seeing tag==t+1 guarantees the h in the same word is current.
//   warps 4-7 (128 lanes): 4 PARALLEL spin loops per lane on
//       ld.acquire.gpu.u64; the hit itself carries the data -> h_sh.
//   syncB
__global__ void __launch_bounds__(256, 1) lstm_kernel(
    const float* __restrict__ Whh_f,
    const float* __restrict__ Whh_b)
{
    const int bx  = blockIdx.x;
    const int dir = bx >> 5;
    const int b   = bx & 31;
    const float* Whh = dir ? Whh_b : Whh_f;
    const float* xg  = d_xg[dir];
    unsigned long long* Hx = d_Hx[dir];

    const int tid = threadIdx.x;
    const int w = tid >> 5, l = tid & 31;
    const int cc = w >> 1;                  // 0..3 column chunk (128 cols)
    const int lr = (w & 1) * 32 + l;        // 0..63 local gate row
    const int grow = ((lr >> 4) << 9) + b * 16 + (lr & 15);  // global gate row

    // weights: 128 fp32 per thread, packed as 64 u64 pairs for FFMA2
    unsigned long long wreg[64];
    {
        const ulonglong2* wp =
            (const ulonglong2*)(Whh + (long long)grow * HID + cc * 128);
#pragma unroll
        for (int i = 0; i < 32; i++) {
            ulonglong2 v = wp[i];
            wreg[2 * i]     = v.x;
            wreg[2 * i + 1] = v.y;
        }
    }

    __shared__ __align__(16) float h_sh[HID];
    __shared__ float part[4][64];

    float c = 0.f;                 // cell state (warp 0 lanes 0-15)
    float xgv[4] = {0.f, 0.f, 0.f, 0.f};

    h_sh[tid] = 0.f;
    h_sh[tid + 256] = 0.f;
    if (w == 0 && l < 16) {
        int t0 = dir ? (T - 1) : 0;
#pragma unroll
        for (int g = 0; g < 4; g++)
            xgv[g] = xg[(long long)t0 * G4 + (g << 9) + b * 16 + l];
    }
    __syncthreads();

    for (int s = 0; s < T; s++) {
        const int t = dir ? (T - 1 - s) : s;
        const unsigned want = (unsigned)t + 1u;

        // ---- partial dot: lane gate-row x 128-col chunk (FFMA2) ----
        {
            unsigned long long a0 = 0ull, a1 = 0ull;
            const ulonglong2* h2 = (const ulonglong2*)(h_sh + (cc << 7));
#pragma unroll
            for (int i = 0; i < 32; i++) {
                ulonglong2 hv = h2[i];   // broadcast LDS.128 (uniform address)
                FMA2(a0, wreg[2 * i],     hv.x, a0);
                FMA2(a1, wreg[2 * i + 1], hv.y, a1);
            }
            float x0, x1, x2, x3;
            asm("mov.b64 {%0,%1}, %2;" : "=f"(x0), "=f"(x1) : "l"(a0));
            asm("mov.b64 {%0,%1}, %2;" : "=f"(x2), "=f"(x3) : "l"(a1));
            part[cc][lr] = (x0 + x1) + (x2 + x3);
        }
        __syncthreads();   // A: all partials in smem

        if (w == 0) {
            if (l < 16) {
                float g0 = part[0][l]      + part[1][l]      + part[2][l]      + part[3][l]      + xgv[0];
                float g1 = part[0][16 + l] + part[1][16 + l] + part[2][16 + l] + part[3][16 + l] + xgv[1];
                float g2 = part[0][32 + l] + part[1][32 + l] + part[2][32 + l] + part[3][32 + l] + xgv[2];
                float g3 = part[0][48 + l] + part[1][48 + l] + part[2][48 + l] + part[3][48 + l] + xgv[3];

                float ig = __fdividef(1.f, 1.f + __expf(-g0));
                float fg = __fdividef(1.f, 1.f + __expf(-g1));
                float og = __fdividef(1.f, 1.f + __expf(-g3));
                float tg = __fdividef(2.f, 1.f + __expf(-2.f * g2)) - 1.f;
                c = fg * c + ig * tg;
                float th = __fdividef(2.f, 1.f + __expf(-2.f * c)) - 1.f;
                float hh = og * th;

                // ONE strong ST.64: (t+1)<<32 | h_bits, release scope gpu
                unsigned long long pv =
                    ((unsigned long long)want << 32) |
                    (unsigned long long)__float_as_uint(hh);
                unsigned long long* hp = Hx + (long long)t * HID + b * 16 + l;
                asm volatile("st.release.gpu.global.u64 [%0], %1;"
                             :: "l"(hp), "l"(pv) : "memory");

                // prefetch next step's xg (a full step of latency slack)
                if (s + 1 < T) {
                    int tn = dir ? (t - 1) : (t + 1);
#pragma unroll
                    for (int g = 0; g < 4; g++)
                        xgv[g] = __ldcg(xg + (long long)tn * G4 + (g << 9) + b * 16 + l);
                }
            }
        } else if (w >= 4 && s + 1 < T) {
            // ---- 4 PARALLEL acquire spin loops per lane ----
            const int cidx = ((w - 4) << 5) + l;           // 0..127
            const unsigned long long* base = Hx + (long long)t * HID;
            const unsigned long long* p0 = base + cidx;
            const unsigned long long* p1 = base + 128 + cidx;
            const unsigned long long* p2 = base + 256 + cidx;
            const unsigned long long* p3 = base + 384 + cidx;
            unsigned long long v0 = 0, v1 = 0, v2 = 0, v3 = 0;
            bool d0 = false, d1 = false, d2 = false, d3 = false;
            do {
                if (!d0) {
                    asm volatile("ld.acquire.gpu.global.u64 %0, [%1];"
                                 : "=l"(v0) : "l"(p0) : "memory");
                    d0 = (unsigned)(v0 >> 32) == want;
                }
                if (!d1) {
                    asm volatile("ld.acquire.gpu.global.u64 %0, [%1];"
                                 : "=l"(v1) : "l"(p1) : "memory");
                    d1 = (unsigned)(v1 >> 32) == want;
                }
                if (!d2) {
                    asm volatile("ld.acquire.gpu.global.u64 %0, [%1];"
                                 : "=l"(v2) : "l"(p2) : "memory");
                    d2 = (unsigned)(v2 >> 32) == want;
                }
                if (!d3) {
                    asm volatile("ld.acquire.gpu.global.u64 %0, [%1];"
                                 : "=l"(v3) : "l"(p3) : "memory");
                    d3 = (unsigned)(v3 >> 32) == want;
                }
            } while (!(d0 && d1 && d2 && d3));
            h_sh[cidx]       = __uint_as_float((unsigned)v0);
            h_sh[128 + cidx] = __uint_as_float((unsigned)v1);
            h_sh[256 + cidx] = __uint_as_float((unsigned)v2);
            h_sh[384 + cidx] = __uint_as_float((unsigned)v3);
        }
        __syncthreads();   // B: h(t) staged in smem for next step
    }
}

// ---------------- feats = [h_f, h_b] @ W_out^T + b_out ----------------
// Reads h out of the packed array: float4 = (h0,tag0,h1,tag1) in fp32 lanes.
__global__ void __launch_bounds__(128) feats_kernel(
    const float* __restrict__ W_out,
    const float* __restrict__ b_out)
{
    __shared__ __align__(16) float hb[2 * HID];
    int tid = threadIdx.x;
    int r = tid >> 3, cs = tid & 7;

    for (int tt = 0; tt < 32; tt++) {
        int t = blockIdx.x * 32 + tt;
        __syncthreads();
#pragma unroll
        for (int dir = 0; dir < 2; dir++) {
            const float4* src = (const float4*)(d_Hx[dir] + (long long)t * HID);
#pragma unroll
            for (int k = 0; k < 2; k++) {
                int i = k * 128 + tid;           // 0..255 float4s (= 512 packed words)
                float4 v = src[i];
                hb[dir * HID + 2 * i]     = v.x;  // h lives in the low word
                hb[dir * HID + 2 * i + 1] = v.z;
            }
        }
        __syncthreads();
        if (tid < 96) {
            const float4* wv = (const float4*)(W_out + r * 1024 + cs * 128);
            const float4* hv = (const float4*)(hb + cs * 128);
            float s0 = 0.f, s1 = 0.f, s2 = 0.f, s3 = 0.f;
#pragma unroll
            for (int i = 0; i < 32; i++) {
                float4 a = __ldg(wv + i);
                float4 bq = hv[i];
                s0 += a.x * bq.x; s1 += a.y * bq.y;
                s2 += a.z * bq.z; s3 += a.w * bq.w;
            }
            float sum = (s0 + s1) + (s2 + s3);
#pragma unroll
            for (int o = 4; o >= 1; o >>= 1)
                sum += __shfl_down_sync(0xffffffffu, sum, o);
            if (cs == 0)
                d_feats[t * TAGS + r] = sum + b_out[r];
        }
    }
}

// ---------------- Viterbi: forward scan + packed backtrace ----------------
__global__ void viterbi_kernel(const float* __restrict__ trans,
                               float* __restrict__ out)
{
    __shared__ unsigned long long bps[T];
    int l = threadIdx.x;

    float tr[TAGS];
    if (l < TAGS) {
#pragma unroll
        for (int p = 0; p < TAGS; p++) tr[p] = trans[l * TAGS + p];
    } else {
#pragma unroll
        for (int p = 0; p < TAGS; p++) tr[p] = 0.f;
    }

    float fv = (l == 10) ? 0.f : NEGV;   // START = 10
    float featnext = (l < TAGS) ? d_feats[l] : 0.f;

    for (int t = 0; t < T; t++) {
        float feat = featnext;
        if (t + 1 < T && l < TAGS) featnext = d_feats[(t + 1) * TAGS + l];

        float m = -3.4e38f; int am = 0;
#pragma unroll
        for (int p = 0; p < TAGS; p++) {
            float v = __shfl_sync(0xffffffffu, fv, p) + tr[p];
            if (v > m) { m = v; am = p; }
        }
        unsigned lo = (l < 8)              ? ((unsigned)am << (4 * l))       : 0u;
        unsigned hi = (l >= 8 && l < TAGS) ? ((unsigned)am << (4 * (l - 8))) : 0u;
        lo = __reduce_add_sync(0xffffffffu, lo);
        hi = __reduce_add_sync(0xffffffffu, hi);
        if (l == 0) d_bp[t] = ((unsigned long long)hi << 32) | lo;

        fv = m + feat;
    }

    float term;
    if (l < TAGS) term = fv + trans[11 * TAGS + l];
    else          term = -3.4e38f;
    if (l == 11 || l == 10) term = NEGV;

    int best = 0; float sc = -3.4e38f;
#pragma unroll
    for (int p = 0; p < TAGS; p++) {
        float v = __shfl_sync(0xffffffffu, term, p);
        if (v > sc) { sc = v; best = p; }
    }

    for (int i = l; i < T; i += 32) bps[i] = d_bp[i];
    __syncwarp();

    if (l == 0) {
        out[0] = sc;
        out[T] = (float)best;            // path[T-1]
        int tag = best;
        for (int t = T - 1; t >= 1; t--) {
            int prev = (int)((bps[t] >> (4 * tag)) & 15ull);
            out[t] = (float)prev;        // path[t-1] = chain[t]
            tag = prev;
        }
    }
}

// ---------------- launch ----------------
extern "C" void kernel_launch(void* const* d_in, const int* in_sizes, int n_in,
                              void* d_out, int out_size)
{
    const int*   sent  = (const int*)d_in[0];
    const float* embt  = (const float*)d_in[1];
    const float* Wih_f = (const float*)d_in[2];
    const float* Whh_f = (const float*)d_in[3];
    const float* bih_f = (const float*)d_in[4];
    const float* bhh_f = (const float*)d_in[5];
    const float* Wih_b = (const float*)d_in[6];
    const float* Whh_b = (const float*)d_in[7];
    const float* bih_b = (const float*)d_in[8];
    const float* bhh_b = (const float*)d_in[9];
    const float* W_out = (const float*)d_in[10];
    const float* b_out = (const float*)d_in[11];
    const float* trans = (const float*)d_in[12];
    float* out = (float*)d_out;

    init_kernel<<<2048, 1024>>>();
    dim3 g(T / 32, G4 / 256);
    xg_kernel<<<g, 256>>>(0, sent, embt, Wih_f, bih_f, bhh_f);
    xg_kernel<<<g, 256>>>(1, sent, embt, Wih_b, bih_b, bhh_b);
    lstm_kernel<<<2 * NB, 256>>>(Whh_f, Whh_b);
    feats_kernel<<<128, 128>>>(W_out, b_out);
    viterbi_kernel<<<1, 32>>>(trans, out);
}